// round 5
// baseline (speedup 1.0000x reference)
#include <cuda_runtime.h>

// DifferentiableDrone: batched RK4 step of 12-state quadrotor dynamics.
// One thread per row. Shared-memory staging for coalesced 48B-row I/O.
// Pitch trig uses PRECISE sincosf: t_pitch = s_p/c_p is singularity-amplified
// (|c_p| down to ~4e-6 over 2M N(0,1) samples) and needs RELATIVE accuracy;
// the fast __sincosf has only an absolute error bound and fails there.

#define DT_F     0.01f
#define K_DRAG_F 0.05f

__device__ __forceinline__ void dyn(
    const float* __restrict__ s,
    float T, float taux, float tauy, float tauz,
    float Ix, float Iy, float Iz,
    float iIx, float iIy, float iIz,
    float gx, float gy, float gz,
    float* __restrict__ o)
{
    float vx = s[3], vy = s[4], vz = s[5];
    float wx = s[9], wy = s[10], wz = s[11];

    float s_r, c_r, s_p, c_p, s_y, c_y;
    __sincosf(s[6], &s_r, &c_r);   // roll: absolute 3e-7 error is harmless
    sincosf(s[7], &s_p, &c_p);     // pitch: PRECISE (relative-accurate near zeros)
    __sincosf(s[8], &s_y, &c_y);   // yaw: absolute error harmless

    // pos_dot = vel
    o[0] = vx; o[1] = vy; o[2] = vz;

    // acc = R[:,2]*T + drag + g   (M = 1)
    float n2 = vx * vx + vy * vy + vz * vz;
    float n  = fmaxf(sqrtf(n2), 1e-8f);
    float d  = -K_DRAG_F * n;
    float r02 = c_y * s_p * c_r + s_y * s_r;
    float r12 = s_y * s_p * c_r - c_y * s_r;
    float r22 = c_p * c_r;
    o[3] = r02 * T + d * vx + gx;
    o[4] = r12 * T + d * vy + gy;
    o[5] = r22 * T + d * vz + gz;

    // att_dot (Euler kinematics, with reference's cos(pitch) clamp)
    float c_pit = (fabsf(c_p) < 1e-6f) ? 1e-6f : c_p;
    float icp   = __fdividef(1.0f, c_pit);   // ulp-accurate relative: safe
    float srwy_crwz = s_r * wy + c_r * wz;
    o[6] = wx + srwy_crwz * (s_p * icp);
    o[7] = c_r * wy - s_r * wz;
    o[8] = srwy_crwz * icp;

    // omega_dot = (tau - omega x (I*omega)) / I
    float cx = wy * (wz * Iz) - wz * (wy * Iy);
    float cy = wz * (wx * Ix) - wx * (wz * Iz);
    float cz = wx * (wy * Iy) - wy * (wx * Ix);
    o[9]  = (taux - cx) * iIx;
    o[10] = (tauy - cy) * iIy;
    o[11] = (tauz - cz) * iIz;
}

__global__ void __launch_bounds__(256)
drone_rk4_kernel(const float4* __restrict__ g_state,
                 const float4* __restrict__ g_u,
                 const float*  __restrict__ g_I,
                 const float*  __restrict__ g_g,
                 float4* __restrict__ g_out,
                 int B)
{
    __shared__ float4 buf[768];   // 256 rows x 3 float4 = 12 KB

    const int tid     = threadIdx.x;
    const int rowBase = blockIdx.x * 256;
    const int f4Base  = rowBase * 3;
    const int totalF4 = B * 3;

    // uniform constants
    const float Ix = __ldg(g_I + 0), Iy = __ldg(g_I + 1), Iz = __ldg(g_I + 2);
    const float gx = __ldg(g_g + 0), gy = __ldg(g_g + 1), gz = __ldg(g_g + 2);
    const float iIx = __fdividef(1.0f, Ix);
    const float iIy = __fdividef(1.0f, Iy);
    const float iIz = __fdividef(1.0f, Iz);

    // coalesced staged load of 256 rows of state
    #pragma unroll
    for (int i = 0; i < 3; i++) {
        int idx = f4Base + tid + i * 256;
        if (idx < totalF4) buf[tid + i * 256] = g_state[idx];
    }
    __syncthreads();

    const int row = rowBase + tid;
    float out[12];

    if (row < B) {
        float y[12];
        const float* p = (const float*)&buf[tid * 3];
        #pragma unroll
        for (int i = 0; i < 12; i++) y[i] = p[i];

        float4 uu = g_u[row];   // 16B stride: already perfectly coalesced

        float k[12], ks[12], tmp[12];

        // k1
        dyn(y, uu.x, uu.y, uu.z, uu.w, Ix, Iy, Iz, iIx, iIy, iIz, gx, gy, gz, k);
        #pragma unroll
        for (int i = 0; i < 12; i++) {
            ks[i]  = k[i];
            tmp[i] = fmaf(0.5f * DT_F, k[i], y[i]);
        }
        // k2
        dyn(tmp, uu.x, uu.y, uu.z, uu.w, Ix, Iy, Iz, iIx, iIy, iIz, gx, gy, gz, k);
        #pragma unroll
        for (int i = 0; i < 12; i++) {
            ks[i] += 2.0f * k[i];
            tmp[i] = fmaf(0.5f * DT_F, k[i], y[i]);
        }
        // k3
        dyn(tmp, uu.x, uu.y, uu.z, uu.w, Ix, Iy, Iz, iIx, iIy, iIz, gx, gy, gz, k);
        #pragma unroll
        for (int i = 0; i < 12; i++) {
            ks[i] += 2.0f * k[i];
            tmp[i] = fmaf(DT_F, k[i], y[i]);
        }
        // k4
        dyn(tmp, uu.x, uu.y, uu.z, uu.w, Ix, Iy, Iz, iIx, iIy, iIz, gx, gy, gz, k);
        #pragma unroll
        for (int i = 0; i < 12; i++)
            out[i] = fmaf(DT_F / 6.0f, ks[i] + k[i], y[i]);
    }

    __syncthreads();   // smem buffer reuse for output staging

    if (row < B) {
        float* p = (float*)&buf[tid * 3];
        #pragma unroll
        for (int i = 0; i < 12; i++) p[i] = out[i];
    }
    __syncthreads();

    // coalesced staged store
    #pragma unroll
    for (int i = 0; i < 3; i++) {
        int idx = f4Base + tid + i * 256;
        if (idx < totalF4) g_out[idx] = buf[tid + i * 256];
    }
}

extern "C" void kernel_launch(void* const* d_in, const int* in_sizes, int n_in,
                              void* d_out, int out_size)
{
    const float4* g_state = (const float4*)d_in[0];
    const float4* g_u     = (const float4*)d_in[1];
    const float*  g_I     = (const float*)d_in[2];
    const float*  g_g     = (const float*)d_in[3];
    float4* g_out = (float4*)d_out;

    int B = in_sizes[0] / 12;
    int grid = (B + 255) / 256;
    drone_rk4_kernel<<<grid, 256>>>(g_state, g_u, g_I, g_g, g_out, B);
}

// round 6
// speedup vs baseline: 1.0554x; 1.0554x over previous
#include <cuda_runtime.h>

// DifferentiableDrone: batched RK4 step of 12-state quadrotor dynamics.
// One thread per row. Shared-memory staging for coalesced 48B-row I/O.
//
// Trig strategy: fast __sincosf everywhere; c_p (cos pitch) is fixed up with
// an inline Cody-Waite precise path ONLY when |c_p| < 0.01, because
// t_pitch = s_p/c_p amplifies c_p's RELATIVE error ~1e5x near the Euler
// singularity (|c_p| down to ~4e-6 over 2M N(0,1) samples). ~0.5% of threads
// take the fixup; it is call-free (~12 ops).

#define DT_F     0.01f
#define K_DRAG_F 0.05f

// pi/2 split: PIO2_HI is float(pi/2); PIO2_LO = pi/2 - PIO2_HI (to ~1e-15)
#define PIO2_HI  1.57079637050628662109375f
#define PIO2_LO -4.37113883e-8f
#define TWO_OVER_PI 0.636619772367581343f

__device__ __forceinline__ float cos_precise_near_zero(float p)
{
    // p is within ~0.011 of an odd multiple of pi/2 (|p| <= ~6 here).
    float k = rintf(p * TWO_OVER_PI);        // odd integer
    float r = fmaf(-k, PIO2_HI, p);          // exact-ish residual
    r = fmaf(-k, PIO2_LO, r);                // |r| < ~0.011, err ~1e-15+ulp
    // cos(k*pi/2 + r) = -sin(r) if k==1 (mod 4), +sin(r) if k==3 (mod 4)
    float r2 = r * r;
    float s  = r * fmaf(r2, fmaf(r2, 8.3333338e-3f, -1.6666667e-1f), 1.0f); // sin(r)
    int ki = (int)k;
    return (ki & 2) ? s : -s;
}

__device__ __forceinline__ void dyn(
    const float* __restrict__ s,
    float T, float taux, float tauy, float tauz,
    float Ix, float Iy, float Iz,
    float iIx, float iIy, float iIz,
    float gx, float gy, float gz,
    float* __restrict__ o)
{
    float vx = s[3], vy = s[4], vz = s[5];
    float wx = s[9], wy = s[10], wz = s[11];

    float s_r, c_r, s_p, c_p, s_y, c_y;
    __sincosf(s[6], &s_r, &c_r);
    __sincosf(s[7], &s_p, &c_p);
    __sincosf(s[8], &s_y, &c_y);

    // singularity fixup: restore relative accuracy of c_p near its zeros
    if (fabsf(c_p) < 0.01f) c_p = cos_precise_near_zero(s[7]);

    // pos_dot = vel
    o[0] = vx; o[1] = vy; o[2] = vz;

    // acc = R[:,2]*T + drag + g   (M = 1)
    float n2 = vx * vx + vy * vy + vz * vz;
    float n  = fmaxf(sqrtf(n2), 1e-8f);
    float d  = -K_DRAG_F * n;
    float r02 = c_y * s_p * c_r + s_y * s_r;
    float r12 = s_y * s_p * c_r - c_y * s_r;
    float r22 = c_p * c_r;
    o[3] = r02 * T + d * vx + gx;
    o[4] = r12 * T + d * vy + gy;
    o[5] = r22 * T + d * vz + gz;

    // att_dot (Euler kinematics, with reference's cos(pitch) clamp)
    float c_pit = (fabsf(c_p) < 1e-6f) ? 1e-6f : c_p;
    float icp   = __fdividef(1.0f, c_pit);   // ulp-accurate relative: safe
    float srwy_crwz = s_r * wy + c_r * wz;
    o[6] = wx + srwy_crwz * (s_p * icp);
    o[7] = c_r * wy - s_r * wz;
    o[8] = srwy_crwz * icp;

    // omega_dot = (tau - omega x (I*omega)) / I
    float cx = wy * (wz * Iz) - wz * (wy * Iy);
    float cy = wz * (wx * Ix) - wx * (wz * Iz);
    float cz = wx * (wy * Iy) - wy * (wx * Ix);
    o[9]  = (taux - cx) * iIx;
    o[10] = (tauy - cy) * iIy;
    o[11] = (tauz - cz) * iIz;
}

__global__ void __launch_bounds__(256)
drone_rk4_kernel(const float4* __restrict__ g_state,
                 const float4* __restrict__ g_u,
                 const float*  __restrict__ g_I,
                 const float*  __restrict__ g_g,
                 float4* __restrict__ g_out,
                 int B)
{
    __shared__ float4 buf[768];   // 256 rows x 3 float4 = 12 KB

    const int tid     = threadIdx.x;
    const int rowBase = blockIdx.x * 256;
    const int f4Base  = rowBase * 3;
    const int totalF4 = B * 3;

    // uniform constants
    const float Ix = __ldg(g_I + 0), Iy = __ldg(g_I + 1), Iz = __ldg(g_I + 2);
    const float gx = __ldg(g_g + 0), gy = __ldg(g_g + 1), gz = __ldg(g_g + 2);
    const float iIx = __fdividef(1.0f, Ix);
    const float iIy = __fdividef(1.0f, Iy);
    const float iIz = __fdividef(1.0f, Iz);

    // coalesced staged load of 256 rows of state
    #pragma unroll
    for (int i = 0; i < 3; i++) {
        int idx = f4Base + tid + i * 256;
        if (idx < totalF4) buf[tid + i * 256] = g_state[idx];
    }
    __syncthreads();

    const int row = rowBase + tid;
    float out[12];

    if (row < B) {
        float y[12];
        const float* p = (const float*)&buf[tid * 3];
        #pragma unroll
        for (int i = 0; i < 12; i++) y[i] = p[i];

        float4 uu = g_u[row];   // 16B stride: already perfectly coalesced

        float k[12], ks[12], tmp[12];

        // k1
        dyn(y, uu.x, uu.y, uu.z, uu.w, Ix, Iy, Iz, iIx, iIy, iIz, gx, gy, gz, k);
        #pragma unroll
        for (int i = 0; i < 12; i++) {
            ks[i]  = k[i];
            tmp[i] = fmaf(0.5f * DT_F, k[i], y[i]);
        }
        // k2
        dyn(tmp, uu.x, uu.y, uu.z, uu.w, Ix, Iy, Iz, iIx, iIy, iIz, gx, gy, gz, k);
        #pragma unroll
        for (int i = 0; i < 12; i++) {
            ks[i] += 2.0f * k[i];
            tmp[i] = fmaf(0.5f * DT_F, k[i], y[i]);
        }
        // k3
        dyn(tmp, uu.x, uu.y, uu.z, uu.w, Ix, Iy, Iz, iIx, iIy, iIz, gx, gy, gz, k);
        #pragma unroll
        for (int i = 0; i < 12; i++) {
            ks[i] += 2.0f * k[i];
            tmp[i] = fmaf(DT_F, k[i], y[i]);
        }
        // k4
        dyn(tmp, uu.x, uu.y, uu.z, uu.w, Ix, Iy, Iz, iIx, iIy, iIz, gx, gy, gz, k);
        #pragma unroll
        for (int i = 0; i < 12; i++)
            out[i] = fmaf(DT_F / 6.0f, ks[i] + k[i], y[i]);
    }

    __syncthreads();   // smem buffer reuse for output staging

    if (row < B) {
        float* p = (float*)&buf[tid * 3];
        #pragma unroll
        for (int i = 0; i < 12; i++) p[i] = out[i];
    }
    __syncthreads();

    // coalesced staged store
    #pragma unroll
    for (int i = 0; i < 3; i++) {
        int idx = f4Base + tid + i * 256;
        if (idx < totalF4) g_out[idx] = buf[tid + i * 256];
    }
}

extern "C" void kernel_launch(void* const* d_in, const int* in_sizes, int n_in,
                              void* d_out, int out_size)
{
    const float4* g_state = (const float4*)d_in[0];
    const float4* g_u     = (const float4*)d_in[1];
    const float*  g_I     = (const float*)d_in[2];
    const float*  g_g     = (const float*)d_in[3];
    float4* g_out = (float4*)d_out;

    int B = in_sizes[0] / 12;
    int grid = (B + 255) / 256;
    drone_rk4_kernel<<<grid, 256>>>(g_state, g_u, g_I, g_g, g_out, B);
}